// round 17
// baseline (speedup 1.0000x reference)
#include <cuda_runtime.h>
#include <cuda_fp16.h>
#include <math.h>

// Problem constants
#define BB 8
#define LL 1024
#define DD 512
#define HH 8
#define DH 64
#define INNER 512
#define ROWS (BB*LL)          // 8192
#define EPSV 1e-5f
#define SCALE_LOG2E 0.18033688011112042f   // 0.125 * log2(e)

// ---------------- scratch (device globals; no allocation) ----------------
__device__ __half  g_xn [ROWS*DD];
__device__ __half  g_pe [LL*DD];
__device__ __half  g_pos[HH*LL*DH];
__device__ __half  g_q  [BB*HH*LL*DH];
__device__ __half  g_k  [BB*HH*LL*DH];
__device__ __half  g_v  [BB*HH*DH*LL];     // TRANSPOSED: [bh][dh][l]
__device__ __half  g_att[ROWS*INNER];
__device__ __half  g_wqkv[3*INNER*DD];
__device__ __half  g_wpos[INNER*DD];
__device__ __half  g_wout[DD*INNER];
__device__ double  g_freq[DD];

// ---------------- helpers ----------------
__device__ __forceinline__ void mma_f16(float c[4], const unsigned a[4], const unsigned b[2]) {
    asm volatile(
        "mma.sync.aligned.m16n8k16.row.col.f32.f16.f16.f32 "
        "{%0,%1,%2,%3}, {%4,%5,%6,%7}, {%8,%9}, {%0,%1,%2,%3};"
        : "+f"(c[0]), "+f"(c[1]), "+f"(c[2]), "+f"(c[3])
        : "r"(a[0]), "r"(a[1]), "r"(a[2]), "r"(a[3]), "r"(b[0]), "r"(b[1]));
}

__device__ __forceinline__ void ldsm4(unsigned r[4], const __half* p) {
    unsigned addr = (unsigned)__cvta_generic_to_shared((void*)p);
    asm volatile("ldmatrix.sync.aligned.m8n8.x4.shared.b16 {%0,%1,%2,%3}, [%4];"
        : "=r"(r[0]), "=r"(r[1]), "=r"(r[2]), "=r"(r[3]) : "r"(addr));
}

__device__ __forceinline__ unsigned pack_h2(float x, float y) {
    unsigned r;
    asm("cvt.rn.f16x2.f32 %0, %1, %2;" : "=r"(r) : "f"(y), "f"(x));
    return r;
}

__device__ __forceinline__ float ex2(float x) {
    float r;
    asm("ex2.approx.ftz.f32 %0, %1;" : "=f"(r) : "f"(x));
    return r;
}

// two fp16 2^x in one MUFU op
__device__ __forceinline__ unsigned ex2_h2(unsigned x) {
    unsigned r;
    asm("ex2.approx.f16x2 %0, %1;" : "=r"(r) : "r"(x));
    return r;
}

__device__ __forceinline__ void cpa16(void* dst_smem, const void* src) {
    unsigned d = (unsigned)__cvta_generic_to_shared(dst_smem);
    asm volatile("cp.async.cg.shared.global [%0], [%1], 16;" :: "r"(d), "l"(src));
}
#define CP_COMMIT asm volatile("cp.async.commit_group;")
#define CP_WAIT0  asm volatile("cp.async.wait_group 0;")
#define CP_WAIT1  asm volatile("cp.async.wait_group 1;")

// ---------------- freq table (tiny, must precede fused kernel) ------------
__global__ void freq_kernel() {
    int j = threadIdx.x + blockIdx.x * blockDim.x;
    if (j < DD) g_freq[j] = exp(-(double)j * (log(10000.0) / 256.0));
}

// ---------------- fused LayerNorm + PE table + weight conversion ----------
#define LN_BLKS   (ROWS / 8)              // 1024
#define PE_BLKS   ((LL * DD) / 256)       // 2048
#define CVT_N4    ((3*INNER*DD + INNER*DD + DD*INNER) / 4)   // 327680
#define CVT_BLKS  ((CVT_N4 + 255) / 256)  // 1280
__global__ void ln_pe_cvt_kernel(const float* __restrict__ x,
                                 const float* __restrict__ gamma,
                                 const float* __restrict__ beta,
                                 const float* __restrict__ wq,
                                 const float* __restrict__ wp,
                                 const float* __restrict__ wo) {
    int tid = threadIdx.x, lane = tid & 31, warp = tid >> 5;
    if (blockIdx.x < LN_BLKS) {
        int row = blockIdx.x * 8 + warp;
        const float* xr = x + (size_t)row * DD;
        float4 v[4];
        float s = 0.f, sq = 0.f;
        #pragma unroll
        for (int k = 0; k < 4; k++) {
            v[k] = *(const float4*)(xr + k * 128 + lane * 4);
            s  += v[k].x + v[k].y + v[k].z + v[k].w;
            sq += v[k].x*v[k].x + v[k].y*v[k].y + v[k].z*v[k].z + v[k].w*v[k].w;
        }
        #pragma unroll
        for (int o = 16; o; o >>= 1) {
            s  += __shfl_xor_sync(0xffffffffu, s,  o);
            sq += __shfl_xor_sync(0xffffffffu, sq, o);
        }
        float mu  = s * (1.f / DD);
        float var = fmaxf(sq * (1.f / DD) - mu * mu, 0.f);
        float rs  = rsqrtf(var + EPSV);
        __half* o = g_xn + (size_t)row * DD;
        #pragma unroll
        for (int k = 0; k < 4; k++) {
            int c = k * 128 + lane * 4;
            float4 gm = *(const float4*)(gamma + c);
            float4 bt = *(const float4*)(beta + c);
            *(__half2*)(o + c)     = __floats2half2_rn((v[k].x - mu)*rs*gm.x + bt.x,
                                                       (v[k].y - mu)*rs*gm.y + bt.y);
            *(__half2*)(o + c + 2) = __floats2half2_rn((v[k].z - mu)*rs*gm.z + bt.z,
                                                       (v[k].w - mu)*rs*gm.w + bt.w);
        }
    } else if (blockIdx.x < LN_BLKS + PE_BLKS) {
        int idx = (blockIdx.x - LN_BLKS) * 256 + tid;
        int i = idx >> 9;
        int j = idx & 511;
        double angle = (double)(i - j) * g_freq[j];
        double n = rint(angle * 0.15915494309189535);   // 1/(2*pi)
        double r = angle - n * 6.283185307179586;       // reduced to [-pi, pi]
        float rf = (float)r;
        g_pe[idx] = __float2half_rn(((j & 1) == 0) ? cosf(rf) : sinf(rf));
    } else {
        const int n1 = 3*INNER*DD/4, n2 = INNER*DD/4, n3 = DD*INNER/4;
        int i = (blockIdx.x - LN_BLKS - PE_BLKS) * 256 + tid;
        float4 v; __half* dst;
        if (i < n1) {
            v = ((const float4*)wq)[i]; dst = g_wqkv + 4*i;
        } else if (i < n1 + n2) {
            v = ((const float4*)wp)[i - n1]; dst = g_wpos + 4*(i - n1);
        } else if (i < n1 + n2 + n3) {
            v = ((const float4*)wo)[i - n1 - n2]; dst = g_wout + 4*(i - n1 - n2);
        } else return;
        *(__half2*)(dst)     = __floats2half2_rn(v.x, v.y);
        *(__half2*)(dst + 2) = __floats2half2_rn(v.z, v.w);
    }
}

// ---------------- FP16 TC GEMM body: 128x128 tile, K-stage 64, 3-stage pipe
#define HLD 72
#define GSTAGE (128 * HLD)
#define GEMM_SMEM_BYTES (6 * GSTAGE * 2)   // 3 stages x (A+B) halves -> ~108 KB
template<int MODE>
__device__ __forceinline__ void gemm_body(__half* As, __half* Bs,
                        const __half* __restrict__ A, const __half* __restrict__ Bt,
                        const float* __restrict__ bias, float* __restrict__ C,
                        int M, int N, int K, int bxx, int byy) {
    int tid  = threadIdx.x, lane = tid & 31, warp = tid >> 5;
    int wm = warp >> 2, wn = warp & 3;     // 2 x 4, warp tile 64x32
    int g  = lane >> 2, t4 = lane & 3;
    int bm = byy * 128, bn = bxx * 128;
    // LDSM per-lane addressing
    int l15 = lane & 15, lh = (lane >> 4) << 3;                 // A: row, k-half
    int bn8 = lane & 7, bkh = ((lane >> 3) & 1) << 3, bnp = (lane >> 4) << 3; // B

    float c[4][4][4];
    #pragma unroll
    for (int mt = 0; mt < 4; mt++)
        #pragma unroll
        for (int nt = 0; nt < 4; nt++)
            #pragma unroll
            for (int i = 0; i < 4; i++) c[mt][nt][i] = 0.f;

    int nstg = K >> 6;   // K/64 (>= 3 here: 8)
    int ldr = tid >> 1, ldc = (tid & 1) << 5;   // 128 rows x 2 half-chunks(32)
    const __half* pa = A  + (size_t)(bm + ldr) * K + ldc;
    const __half* pb = Bt + (size_t)(bn + ldr) * K + ldc;
    __half* da0 = As + ldr * HLD + ldc;
    __half* db0 = Bs + ldr * HLD + ldc;
    // prologue: stages 0 and 1 (one commit-group each)
    #pragma unroll
    for (int p = 0; p < 2; p++) {
        __half* da = da0 + p * GSTAGE;
        __half* db = db0 + p * GSTAGE;
        cpa16(da, pa); cpa16(da + 8, pa + 8); cpa16(da + 16, pa + 16); cpa16(da + 24, pa + 24);
        cpa16(db, pb); cpa16(db + 8, pb + 8); cpa16(db + 16, pb + 16); cpa16(db + 24, pb + 24);
        CP_COMMIT;
        pa += 64; pb += 64;
    }
    int buf = 0, nbuf = 2;
    for (int s = 0; s < nstg; s++) {
        CP_WAIT1;            // oldest group (stage s) retired; s+1 may fly
        __syncthreads();
        if (s + 2 < nstg) {
            __half* da = da0 + nbuf * GSTAGE;
            __half* db = db0 + nbuf * GSTAGE;
            cpa16(da, pa); cpa16(da + 8, pa + 8); cpa16(da + 16, pa + 16); cpa16(da + 24, pa + 24);
            cpa16(db, pb); cpa16(db + 8, pb + 8); cpa16(db + 16, pb + 16); cpa16(db + 24, pb + 24);
            CP_COMMIT;
            pa += 64; pb += 64;
            nbuf = (nbuf == 2) ? 0 : nbuf + 1;
        }
        const __half* Ab = As + buf * GSTAGE;
        const __half* Bb = Bs + buf * GSTAGE;
        buf = (buf == 2) ? 0 : buf + 1;
        #pragma unroll
        for (int kk = 0; kk < 64; kk += 16) {
            unsigned a[4][4], b01[4], b23[4];
            #pragma unroll
            for (int mt = 0; mt < 4; mt++)
                ldsm4(a[mt], Ab + (wm*64 + mt*16 + l15) * HLD + kk + lh);
            ldsm4(b01, Bb + (wn*32 +      bnp + bn8) * HLD + kk + bkh);
            ldsm4(b23, Bb + (wn*32 + 16 + bnp + bn8) * HLD + kk + bkh);
            #pragma unroll
            for (int mt = 0; mt < 4; mt++) {
                mma_f16(c[mt][0], a[mt], &b01[0]);
                mma_f16(c[mt][1], a[mt], &b01[2]);
                mma_f16(c[mt][2], a[mt], &b23[0]);
                mma_f16(c[mt][3], a[mt], &b23[2]);
            }
        }
        // no trailing barrier: next iteration's leading sync orders reuse
        // (prefetch at iter s writes the buffer computed at iter s-1)
    }

    // epilogue (paired stores where destinations are contiguous)
    #pragma unroll
    for (int mt = 0; mt < 4; mt++) {
        #pragma unroll
        for (int nt = 0; nt < 4; nt++) {
            int r0 = bm + wm*64 + mt*16 + g;
            int c0 = bn + wn*32 + nt*8 + t4*2;
            #pragma unroll
            for (int half_ = 0; half_ < 2; half_++) {
                int r = r0 + (half_ ? 8 : 0);
                float v0 = c[mt][nt][2*half_ + 0] + (bias ? bias[c0]     : 0.f);
                float v1 = c[mt][nt][2*half_ + 1] + (bias ? bias[c0 + 1] : 0.f);
                if (MODE == 0) {
                    *(float2*)(C + (size_t)r * N + c0) = make_float2(v0, v1);
                } else if (MODE == 1) {
                    int which = c0 >> 9, rem = c0 & 511;
                    int h = rem >> 6, dh = rem & 63;
                    int b_ = r >> 10, l = r & 1023;
                    if (which == 0)
                        *(__half2*)(g_q + (((size_t)b_ * HH + h) * LL + l) * DH + dh)
                            = __floats2half2_rn(v0, v1);
                    else if (which == 1)
                        *(__half2*)(g_k + (((size_t)b_ * HH + h) * LL + l) * DH + dh)
                            = __floats2half2_rn(v0, v1);
                    else {  // V transposed: [bh][dh][l] — dh not contiguous
                        g_v[(((size_t)b_ * HH + h) * DH + dh)     * LL + l] = __float2half_rn(v0);
                        g_v[(((size_t)b_ * HH + h) * DH + dh + 1) * LL + l] = __float2half_rn(v1);
                    }
                } else {
                    int h = c0 >> 6, dh = c0 & 63;
                    *(__half2*)(g_pos + ((size_t)h * LL + r) * DH + dh)
                        = __floats2half2_rn(v0, v1);
                }
            }
        }
    }
}

// compact 1D grid: blocks 0..767 = QKV (12 x 64), 768..799 = pos (4 x 8)
__global__ __launch_bounds__(256, 2) void gemm_fused(const float* __restrict__ b_qkv) {
    extern __shared__ __half gsm[];
    __half* As = gsm;
    __half* Bs = gsm + 3 * GSTAGE;
    int bid = blockIdx.x;
    if (bid < 768) {
        gemm_body<1>(As, Bs, g_xn, g_wqkv, b_qkv, nullptr, ROWS, 3*INNER, DD,
                     bid % 12, bid / 12);
    } else {
        int r = bid - 768;
        gemm_body<2>(As, Bs, g_pe, g_wpos, nullptr, nullptr, LL, INNER, DD,
                     r % 4, r / 4);
    }
}

__global__ __launch_bounds__(256, 2) void gemm_out(const float* __restrict__ b_out,
                                                   float* __restrict__ out) {
    extern __shared__ __half gsm[];
    __half* As = gsm;
    __half* Bs = gsm + 3 * GSTAGE;
    gemm_body<0>(As, Bs, g_att, g_wout, b_out, out, ROWS, DD, INNER,
                 blockIdx.x, blockIdx.y);
}

// ---------------- flash attention: log2 softmax, f16x2 ex2, ones-frag li ---
#define ATL  136   // sA / sKP row stride (halves)
#define VTL  72    // sVT row stride (halves)
#define N_SA  (128 * ATL)
#define N_SKP (2 * 64 * ATL)
#define N_SVT (2 * 64 * VTL)
#define ATT_SMEM_BYTES ((N_SA + N_SKP + N_SVT) * 2)   // ~86 KB

__global__ __launch_bounds__(256, 2) void attn_tc(const float* __restrict__ u_bias,
                                                  const float* __restrict__ v_bias) {
    extern __shared__ char smbase[];
    __half* sA  = (__half*)smbase;
    __half* sKP = sA  + N_SA;
    __half* sVT = sKP + N_SKP;

    int tid = threadIdx.x, lane = tid & 31, warp = tid >> 5;
    int g  = lane >> 2, t4 = lane & 3;
    int wr = warp * 16;
    int bh = blockIdx.y, b = bh >> 3, h = bh & 7;
    int q0 = blockIdx.x * 128;
    int l15 = lane & 15, lh = (lane >> 4) << 3;
    int bn8 = lane & 7, bkh = ((lane >> 3) & 1) << 3, bnp = (lane >> 4) << 3;

    // constant ones B-fragment: row 0 of the virtual ones-matrix
    unsigned onesf[2];
    onesf[0] = onesf[1] = (g == 0) ? 0x3C003C00u : 0u;

    const __half* qb  = g_q   + (size_t)bh * LL * DH;
    const __half* kb  = g_k   + (size_t)bh * LL * DH;
    const __half* vtb = g_v   + (size_t)bh * DH * LL;
    const __half* pb  = g_pos + (size_t)h  * LL * DH;

    // hoisted prefetch pointers: thread covers rows m0 and m0+32, column c8
    int m0 = tid >> 3, c8 = (tid & 7) << 3;
    const __half* pk = kb  + (size_t)m0 * DH + c8;
    const __half* pp = pb  + (size_t)m0 * DH + c8;
    const __half* pv = vtb + (size_t)m0 * LL + c8;
    __half* dK0 = sKP + m0 * ATL + c8;
    __half* dV0 = sVT + m0 * VTL + c8;

    // prologue: stage 0
    cpa16(dK0,                pk);
    cpa16(dK0 + 32*ATL,       pk + 32*DH);
    cpa16(dK0 + 64,           pp);
    cpa16(dK0 + 32*ATL + 64,  pp + 32*DH);
    cpa16(dV0,                pv);
    cpa16(dV0 + 32*VTL,       pv + 32*LL);
    CP_COMMIT;
    pk += 64*DH; pp += 64*DH; pv += 64;

    // build sA = (Q+u | Q+v) * 0.125*log2e  (half, vectorized 16B)
    for (int idx = tid; idx < 1024; idx += 256) {
        int r = idx >> 3, cc = (idx & 7) << 3;
        uint4 qv = *(const uint4*)(qb + (size_t)(q0 + r) * DH + cc);
        const float* up = u_bias + h * DH + cc;
        const float* vp = v_bias + h * DH + cc;
        float4 u0 = *(const float4*)(up), u1 = *(const float4*)(up + 4);
        float4 v0 = *(const float4*)(vp), v1 = *(const float4*)(vp + 4);
        float2 qa = __half22float2(*(const __half2*)&qv.x);
        float2 qbv = __half22float2(*(const __half2*)&qv.y);
        float2 qc = __half22float2(*(const __half2*)&qv.z);
        float2 qd = __half22float2(*(const __half2*)&qv.w);
        uint4 wu, wv;
        wu.x = pack_h2((qa.x + u0.x) * SCALE_LOG2E, (qa.y + u0.y) * SCALE_LOG2E);
        wu.y = pack_h2((qbv.x + u0.z) * SCALE_LOG2E, (qbv.y + u0.w) * SCALE_LOG2E);
        wu.z = pack_h2((qc.x + u1.x) * SCALE_LOG2E, (qc.y + u1.y) * SCALE_LOG2E);
        wu.w = pack_h2((qd.x + u1.z) * SCALE_LOG2E, (qd.y + u1.w) * SCALE_LOG2E);
        wv.x = pack_h2((qa.x + v0.x) * SCALE_LOG2E, (qa.y + v0.y) * SCALE_LOG2E);
        wv.y = pack_h2((qbv.x + v0.z) * SCALE_LOG2E, (qbv.y + v0.w) * SCALE_LOG2E);
        wv.z = pack_h2((qc.x + v1.x) * SCALE_LOG2E, (qc.y + v1.y) * SCALE_LOG2E);
        wv.w = pack_h2((qd.x + v1.z) * SCALE_LOG2E, (qd.y + v1.w) * SCALE_LOG2E);
        *(uint4*)(sA + r * ATL + cc)      = wu;
        *(uint4*)(sA + r * ATL + 64 + cc) = wv;
    }

    float mi0 = -INFINITY, mi1 = -INFINITY;
    float o[8][4], osum[4];
    #pragma unroll
    for (int nt = 0; nt < 8; nt++)
        #pragma unroll
        for (int i = 0; i < 4; i++) o[nt][i] = 0.f;
    #pragma unroll
    for (int i = 0; i < 4; i++) osum[i] = 0.f;

    for (int kt = 0; kt < LL / 64; kt++) {
        CP_WAIT0;
        __syncthreads();
        int cur = kt & 1;
        if (kt + 1 < LL / 64) {
            int nb = (kt + 1) & 1;
            __half* dK = dK0 + nb * 64 * ATL;
            __half* dV = dV0 + nb * 64 * VTL;
            cpa16(dK,               pk);
            cpa16(dK + 32*ATL,      pk + 32*DH);
            cpa16(dK + 64,          pp);
            cpa16(dK + 32*ATL + 64, pp + 32*DH);
            cpa16(dV,               pv);
            cpa16(dV + 32*VTL,      pv + 32*LL);
            CP_COMMIT;
            pk += 64*DH; pp += 64*DH; pv += 64;
        }
        const __half* KPb = sKP + cur * 64 * ATL;
        const __half* VTb = sVT + cur * 64 * VTL;

        // scores (log2 units): warp tile 16(m) x 64(n), K=128
        float s[8][4];
        #pragma unroll
        for (int nt = 0; nt < 8; nt++)
            #pragma unroll
            for (int i = 0; i < 4; i++) s[nt][i] = 0.f;
        #pragma unroll
        for (int kk = 0; kk < 128; kk += 16) {
            unsigned a[4];
            ldsm4(a, sA + (wr + l15) * ATL + kk + lh);
            #pragma unroll
            for (int pr = 0; pr < 4; pr++) {
                unsigned bb[4];
                ldsm4(bb, KPb + (pr*16 + bnp + bn8) * ATL + kk + bkh);
                mma_f16(s[2*pr],     a, &bb[0]);
                mma_f16(s[2*pr + 1], a, &bb[2]);
            }
        }

        // register softmax (log2 units)
        float m0f = -INFINITY, m1f = -INFINITY;
        #pragma unroll
        for (int nt = 0; nt < 8; nt++) {
            m0f = fmaxf(m0f, fmaxf(s[nt][0], s[nt][1]));
            m1f = fmaxf(m1f, fmaxf(s[nt][2], s[nt][3]));
        }
        m0f = fmaxf(m0f, __shfl_xor_sync(0xffffffffu, m0f, 1));
        m0f = fmaxf(m0f, __shfl_xor_sync(0xffffffffu, m0f, 2));
        m1f = fmaxf(m1f, __shfl_xor_sync(0xffffffffu, m1f, 1));
        m1f = fmaxf(m1f, __shfl_xor_sync(0xffffffffu, m1f, 2));
        float newm0 = fmaxf(mi0, m0f), newm1 = fmaxf(mi1, m1f);
        float alpha0 = ex2(mi0 - newm0), alpha1 = ex2(mi1 - newm1);
        mi0 = newm0; mi1 = newm1;
        unsigned pa4[4][4];
        #pragma unroll
        for (int nt = 0; nt < 8; nt++) {
            // pack (s - m) as half2, single f16x2 ex2 per pair
            unsigned dlo = pack_h2(s[nt][0] - newm0, s[nt][1] - newm0);
            unsigned dhi = pack_h2(s[nt][2] - newm1, s[nt][3] - newm1);
            pa4[nt >> 1][(nt & 1) ? 2 : 0] = ex2_h2(dlo);
            pa4[nt >> 1][(nt & 1) ? 3 : 1] = ex2_h2(dhi);
        }

        // rescale O + li-accumulator (skip when alpha == 1 warp-uniform:
        // ex2(0) == 1 exactly, multiply-by-1 is identity — bit-exact skip)
        bool need = !__all_sync(0xffffffffu,
                                (alpha0 == 1.f) && (alpha1 == 1.f));
        if (need) {
            #pragma unroll
            for (int nt = 0; nt < 8; nt++) {
                o[nt][0] *= alpha0; o[nt][1] *= alpha0;
                o[nt][2] *= alpha1; o[nt][3] *= alpha1;
            }
            osum[0] *= alpha0; osum[1] *= alpha0;
            osum[2] *= alpha1; osum[3] *= alpha1;
        }
        #pragma unroll
        for (int kc = 0; kc < 4; kc++) {
            #pragma unroll
            for (int pr = 0; pr < 4; pr++) {
                unsigned bb[4];
                ldsm4(bb, VTb + (pr*16 + bnp + bn8) * VTL + kc*16 + bkh);
                mma_f16(o[2*pr],     pa4[kc], &bb[0]);
                mma_f16(o[2*pr + 1], pa4[kc], &bb[2]);
            }
            mma_f16(osum, pa4[kc], onesf);   // col 0 accumulates row-sum
        }
    }

    // finalize: li = osum col0 (held by t4==0 lanes) — broadcast across quad
    int src = lane & ~3;
    float li0 = __shfl_sync(0xffffffffu, osum[0], src);
    float li1 = __shfl_sync(0xffffffffu, osum[2], src);
    float inv0 = 1.f / li0, inv1 = 1.f / li1;
    int r0 = wr + g;
    __half* ob1 = g_att + ((size_t)(b * LL + q0 + r0))     * INNER + h * DH;
    __half* ob2 = g_att + ((size_t)(b * LL + q0 + r0 + 8)) * INNER + h * DH;
    #pragma unroll
    for (int nt = 0; nt < 8; nt++) {
        int dh0 = nt*8 + t4*2;
        *(__half2*)(ob1 + dh0) = __floats2half2_rn(o[nt][0] * inv0, o[nt][1] * inv0);
        *(__half2*)(ob2 + dh0) = __floats2half2_rn(o[nt][2] * inv1, o[nt][3] * inv1);
    }
}

// ---------------- launch ----------------
extern "C" void kernel_launch(void* const* d_in, const int* in_sizes, int n_in,
                              void* d_out, int out_size) {
    const float* x      = (const float*)d_in[0];
    const float* gamma  = (const float*)d_in[1];
    const float* beta   = (const float*)d_in[2];
    const float* w_qkv  = (const float*)d_in[3];
    const float* b_qkv  = (const float*)d_in[4];
    const float* w_pos  = (const float*)d_in[5];
    const float* w_out  = (const float*)d_in[6];
    const float* b_out  = (const float*)d_in[7];
    const float* u_bias = (const float*)d_in[8];
    const float* v_bias = (const float*)d_in[9];
    float* out = (float*)d_out;

    // 1. freq table (tiny)
    freq_kernel<<<2, 256>>>();

    // 2. fused LayerNorm + PE table + weight conversion (one launch)
    ln_pe_cvt_kernel<<<LN_BLKS + PE_BLKS + CVT_BLKS, 256>>>(
        x, gamma, beta, w_qkv, w_pos, w_out);

    // 3. fused QKV GEMM + pos GEMM (compact 1D grid, 3-stage pipeline)
    cudaFuncSetAttribute(gemm_fused, cudaFuncAttributeMaxDynamicSharedMemorySize,
                         GEMM_SMEM_BYTES);
    gemm_fused<<<800, 256, GEMM_SMEM_BYTES>>>(b_qkv);

    // 4. attention
    {
        int smem = ATT_SMEM_BYTES;   // ~86 KB
        cudaFuncSetAttribute(attn_tc, cudaFuncAttributeMaxDynamicSharedMemorySize, smem);
        dim3 grid(LL / 128, BB * HH);
        attn_tc<<<grid, 256, smem>>>(u_bias, v_bias);
    }

    // 5. out projection -> d_out (3-stage pipeline)
    {
        cudaFuncSetAttribute(gemm_out, cudaFuncAttributeMaxDynamicSharedMemorySize,
                             GEMM_SMEM_BYTES);
        dim3 grid(DD / 128, ROWS / 128);
        gemm_out<<<grid, 256, GEMM_SMEM_BYTES>>>(b_out, out);
    }
}